// round 16
// baseline (speedup 1.0000x reference)
#include <cuda_runtime.h>
#include <cstdint>
#include <math.h>

// Problem constants (fixed by setup_inputs)
#define VOCAB   512
#define EMB     256
#define HID     64
#define N_POS   (32 * 4096)   // B * L = 131072
#define N_STEPS 5
#define DT_F32  0.01f         // float32(T_HORIZON / steps)
#define TINY_F  1.17549435082228750797e-38f  // finfo(float32).tiny
#define EPS2    1e-3f         // fast/exact margin; fast abs err <= ~1e-6 always
#define NEG_INF __int_as_float(0xff800000)
#define INV2P23 1.1920928955078125e-7f  // 2^-23 (exact)

struct KeysT { unsigned int k1a[5], k1b[5], k2a[5], k2b[5]; };

// -------- scratch: __device__ globals only --------
__device__ float    g_T[VOCAB * VOCAB];   // intensity table
__device__ uint32_t g_pubm[VOCAB];        // bits-space reject bound per state
__device__ int      g_qpk[N_POS];         // queue: packed (pos<<9)|s0
__device__ uint4    g_qm2a[N_POS];        // queue: m2[0..3]
__device__ uint32_t g_qm2b[N_POS];        // queue: m2[4]
__device__ int      g_qcnt;               // flagged count (zeroed by table kernel)

// ===================== threefry-2x32 (exact JAX schedule) =====================
__device__ __forceinline__ void tf_round(uint32_t& x0, uint32_t& x1, int r) {
    x0 += x1;
    x1 = __funnelshift_l(x1, x1, r);
    x1 ^= x0;
}

__device__ __forceinline__ uint2 tf2x32(uint32_t k0, uint32_t k1,
                                        uint32_t x0, uint32_t x1) {
    uint32_t ks2 = k0 ^ k1 ^ 0x1BD11BDAu;
    x0 += k0; x1 += k1;
    tf_round(x0,x1,13); tf_round(x0,x1,15); tf_round(x0,x1,26); tf_round(x0,x1, 6);
    x0 += k1;  x1 += ks2 + 1u;
    tf_round(x0,x1,17); tf_round(x0,x1,29); tf_round(x0,x1,16); tf_round(x0,x1,24);
    x0 += ks2; x1 += k0 + 2u;
    tf_round(x0,x1,13); tf_round(x0,x1,15); tf_round(x0,x1,26); tf_round(x0,x1, 6);
    x0 += k0;  x1 += k1 + 3u;
    tf_round(x0,x1,17); tf_round(x0,x1,29); tf_round(x0,x1,16); tf_round(x0,x1,24);
    x0 += k1;  x1 += ks2 + 4u;
    tf_round(x0,x1,13); tf_round(x0,x1,15); tf_round(x0,x1,26); tf_round(x0,x1, 6);
    x0 += ks2; x1 += k0 + 5u;
    return make_uint2(x0, x1);
}

static inline uint32_t h_rotl(uint32_t x, int r) { return (x << r) | (x >> (32 - r)); }
static void h_tf2x32(uint32_t k0, uint32_t k1, uint32_t x0, uint32_t x1,
                     uint32_t& o0, uint32_t& o1) {
    uint32_t ks2 = k0 ^ k1 ^ 0x1BD11BDAu;
    static const int R[20] = {13,15,26,6, 17,29,16,24, 13,15,26,6, 17,29,16,24, 13,15,26,6};
    x0 += k0; x1 += k1;
    const uint32_t ks[3] = {k0, k1, ks2};
    for (int g = 0; g < 5; g++) {
        for (int j = 0; j < 4; j++) {
            int r = R[g * 4 + j];
            x0 += x1; x1 = h_rotl(x1, r); x1 ^= x0;
        }
        x0 += ks[(g + 1) % 3];
        x1 += ks[(g + 2) % 3] + (uint32_t)(g + 1);
    }
    o0 = x0; o1 = x1;
}

// partitionable random_bits(32): counter (hi=0, lo=idx), out = o0 ^ o1
__device__ __forceinline__ uint32_t jax_bits32(uint32_t k0, uint32_t k1, uint32_t idx) {
    uint2 r = tf2x32(k0, k1, 0u, idx);
    return r.x ^ r.y;
}

__device__ __forceinline__ float bits_to_u01(uint32_t bits) {
    return __uint_as_float((bits >> 9) | 0x3f800000u) - 1.0f;
}

// bits-space accept threshold (monotone in T); 512 calls total (table kernel)
__device__ __noinline__ uint32_t thr_of(float T) {
    float p = T * DT_F32;
    float e = (float)exp(-(double)p);          // correctly-rounded f32 exp
    float a = 1.0f - e;                        // exact (Sterbenz, e in [0.9,1.1])
    double d = ceil((double)a * 8388608.0);
    d = fmin(fmax(d, 0.0), 8388608.0);
    return (uint32_t)d;
}

// exact accept decision, DP reference chain (rare fallback only)
__device__ __noinline__ bool dp_accept(float T, float u2f) {
    float p = T * DT_F32;
    float e = (float)exp(-(double)p);          // correctly-rounded f32 exp
    float a = 1.0f - e;                        // the reference accept prob
    return u2f < a;                            // u2f == reference u2 bit-exactly
}

// fast gumbel, abs err <= ~1e-6 for ALL u: series in exact d=1-u01 near u->1
__device__ __forceinline__ float gumbel_fast2(float u01, float u) {
    float x;
    if (u01 > 0.99f) {
        float d = 1.0f - u01;   // exact (Sterbenz)
        x = d * fmaf(d, fmaf(d, fmaf(d, 0.25f, 0.33333333f), 0.5f), 1.0f);
    } else {
        x = -__logf(u);
    }
    return -__logf(x);
}

// pass 2 (rare): CR-exact resolve among candidates within EPS2 of the fast max.
__device__ __noinline__ int resolve_exact(const float* __restrict__ row,
                                          uint32_t base, int s,
                                          uint32_t k1a, uint32_t k1b,
                                          float m1, int lane) {
    float e1 = NEG_INF;
    int   ei = VOCAB;
    for (int i = 0; i < 16; i++) {
        int v = (i << 5) + lane;
        if (v == s) continue;
        uint32_t bits = jax_bits32(k1a, k1b, base + (uint32_t)v);
        float u01 = bits_to_u01(bits);
        float u = fmaxf(TINY_F, u01 + TINY_F);
        float candf = row[v] + gumbel_fast2(u01, u);
        if (candf < m1 - EPS2) continue;           // provably not the max
        float r1 = (float)log((double)u);          // CR f32 log
        float r2 = (float)log((double)(-r1));      // CR f32 log
        float cand = row[v] - r2;                  // exact reference chain
        if (cand > e1) { e1 = cand; ei = v; }      // ascending v: first tie
    }
    #pragma unroll
    for (int off = 16; off; off >>= 1) {
        float ov = __shfl_xor_sync(0xffffffffu, e1, off);
        int   oi = __shfl_xor_sync(0xffffffffu, ei, off);
        if (ov > e1 || (ov == e1 && oi < ei)) { e1 = ov; ei = oi; }
    }
    return ei;
}

// one Gillespie step for one position (warp-collective, warp-uniform args)
__device__ __forceinline__ int do_step(int s, uint32_t base, uint32_t m2,
                                       uint32_t k1a, uint32_t k1b, int lane) {
    const float* __restrict__ row = g_T + (s << 9);

    // ---- pass 1: pure-f32 fast gumbels, full ILP ----
    float m1 = NEG_INF, mm2 = NEG_INF;
    int   i1 = VOCAB;
    #pragma unroll
    for (int i = 0; i < 16; i++) {
        int v = (i << 5) + lane;
        uint32_t bits = jax_bits32(k1a, k1b, base + (uint32_t)v);
        float u01 = bits_to_u01(bits);
        float u = fmaxf(TINY_F, u01 + TINY_F);
        float g = gumbel_fast2(u01, u);
        float cand = (v == s) ? NEG_INF : (row[v] + g);
        if (cand > m1) { mm2 = m1; m1 = cand; i1 = v; }
        else if (cand > mm2) { mm2 = cand; }
    }
    #pragma unroll
    for (int off = 16; off; off >>= 1) {
        float o1 = __shfl_xor_sync(0xffffffffu, m1, off);
        int   oi = __shfl_xor_sync(0xffffffffu, i1, off);
        float o2 = __shfl_xor_sync(0xffffffffu, mm2, off);
        if (o1 > m1 || (o1 == m1 && oi < i1)) {
            mm2 = fmaxf(m1, o2); m1 = o1; i1 = oi;
        } else {
            mm2 = fmaxf(mm2, o1);
        }
    }
    int bidx = i1;

    // ---- pass 2 (rare, gap < EPS2): CR-exact resolve near the max ----
    if ((m1 - mm2) < EPS2)
        bidx = resolve_exact(row, base, s, k1a, k1b, m1, lane);

    // ---- accept: fast f32 compare, provable margin, rare DP fallback ----
    float T   = row[bidx];
    float u2f = (float)m2 * INV2P23;                 // exact == ref u2
    float af  = 1.0f - __expf(-(T * DT_F32));        // |af-a_ref| < ~5e-7
    bool acc;
    if (fabsf(u2f - af) > 1e-6f) acc = (u2f < af);   // certain
    else                         acc = dp_accept(T, u2f);
    return acc ? bidx : s;
}

// ===================== io kernels =====================
__global__ void k_fallback(float* __restrict__ out) {
    int i = blockIdx.x * blockDim.x + threadIdx.x;
    if (i < N_POS) out[i] = 1000.0f;
}

// warp-collective classification from a FIXED 32-word window (A[0..31], B[0..31]).
// All blocks read the same 128B -> one cold miss chip-wide, then L1/L2 hits.
// mode: 0 A=x(int), 1 A=x(f32), 2 B=x(int), 3 B=x(f32).
// Emb window passing a state-check: P ~ 0.16^32 ~ 3e-26. All-zero ambiguity
// decodes identically under both encodings.
__device__ __forceinline__ int warp_mode(const uint32_t* __restrict__ A,
                                         const uint32_t* __restrict__ B,
                                         int lane) {
    uint32_t wa = A[lane], wb = B[lane];
    int aInt = __all_sync(0xffffffffu, wa < 512u);
    int aF32 = __all_sync(0xffffffffu, wa == 0u ||
                          (wa >= 0x3f800000u && wa <= 0x43ff8000u));
    int bInt = __all_sync(0xffffffffu, wb < 512u);
    return aInt ? 0 : (aF32 ? 1 : (bInt ? 2 : 3));
}

// ===================== fused table kernel (one block per state) ===============
__global__ void __launch_bounds__(256)
k_table_fused(const uint32_t* __restrict__ A, const uint32_t* __restrict__ B,
              const float* __restrict__ W1, const float* __restrict__ b1,
              const float* __restrict__ W2, const float* __restrict__ b2) {
    __shared__ float sE[EMB];
    __shared__ float sH[HID];
    __shared__ float sMax[8];
    __shared__ int   sMode;
    int s = blockIdx.x;
    int tid = threadIdx.x;
    if (s == 0 && tid == 0) g_qcnt = 0;   // zero queue counter (runs before scan)

    if (tid < 32) {
        int mode = warp_mode(A, B, tid);
        if (tid == 0) sMode = mode;
    }
    __syncthreads();
    const float* emb = (const float*)((sMode < 2) ? B : A);   // the non-x buffer

    if (tid < EMB / 4)
        ((float4*)sE)[tid] = ((const float4*)(emb + s * EMB))[tid];
    __syncthreads();

    if (tid < HID) {
        float acc = 0.0f;
        #pragma unroll 16
        for (int k = 0; k < EMB; k++)
            acc = fmaf(sE[k], W1[k * HID + tid], acc);
        sH[tid] = fmaxf(acc + b1[tid], 0.0f);
    }
    __syncthreads();

    float tmax = NEG_INF;
    #pragma unroll
    for (int r = 0; r < 2; r++) {
        int v = tid + r * 256;
        float acc = 0.0f;
        #pragma unroll
        for (int j = 0; j < HID; j++)
            acc = fmaf(sH[j], W2[j * VOCAB + v], acc);
        float T = acc + b2[v];
        g_T[s * VOCAB + v] = T;
        if (v != s) tmax = fmaxf(tmax, T);
    }
    #pragma unroll
    for (int off = 16; off; off >>= 1)
        tmax = fmaxf(tmax, __shfl_xor_sync(0xffffffffu, tmax, off));
    if ((tid & 31) == 0) sMax[tid >> 5] = tmax;
    __syncthreads();
    if (tid == 0) {
        float m = NEG_INF;
        #pragma unroll
        for (int w = 0; w < 8; w++) m = fmaxf(m, sMax[w]);
        g_pubm[s] = thr_of(m);    // thr monotone in T -> exact row bound
    }
}

// ===================== scan: flag + store m2 payload =========================
// Exact: the FIRST accept must occur from s0, requiring m2_t < pubm[s0].
// Reads ONLY the x buffer (mode from the shared fixed window).
__global__ void __launch_bounds__(256)
k_scan(const uint32_t* __restrict__ A, const uint32_t* __restrict__ B,
       float* __restrict__ outf, KeysT K) {
    int lane = threadIdx.x & 31;
    int mode = warp_mode(A, B, lane);      // L1-hot after first warp
    const uint32_t* xp = (mode < 2) ? A : B;

    int i = blockIdx.x * 256 + threadIdx.x;
    uint32_t w = xp[i];
    int s0 = (mode & 1) ? (int)__uint_as_float(w) : (int)w;
    s0 = min(max(s0, 0), VOCAB - 1);
    outf[i] = (float)s0;

    uint32_t pb = g_pubm[s0];
    uint32_t m2[N_STEPS];
    bool flag = false;
    #pragma unroll
    for (int t = 0; t < N_STEPS; t++) {
        m2[t] = jax_bits32(K.k2a[t], K.k2b[t], (uint32_t)i) >> 9;
        flag |= (m2[t] < pb);
    }
    unsigned mask = __ballot_sync(0xffffffffu, flag);
    if (mask) {
        int leader = __ffs(mask) - 1;
        int baseIdx = 0;
        if (lane == leader) baseIdx = atomicAdd(&g_qcnt, __popc(mask));
        baseIdx = __shfl_sync(0xffffffffu, baseIdx, leader);
        if (flag) {
            int idx = baseIdx + __popc(mask & ((1u << lane) - 1));
            g_qpk[idx]  = (i << 9) | s0;
            g_qm2a[idx] = make_uint4(m2[0], m2[1], m2[2], m2[3]);
            g_qm2b[idx] = m2[4];
        }
    }
}

// ===================== worker: full 5-step trajectory per flagged position ====
__global__ void __launch_bounds__(128, 12)
k_work(float* __restrict__ outf, KeysT K) {
    int gw    = blockIdx.x * 4 + (threadIdx.x >> 5);
    int lane  = threadIdx.x & 31;
    int nwarp = gridDim.x * 4;
    int qn    = min(g_qcnt, N_POS);

    for (int qi = gw; qi < qn; qi += nwarp) {
        int packed   = g_qpk[qi];
        uint4 ma     = g_qm2a[qi];
        uint32_t mb  = g_qm2b[qi];
        int pos = packed >> 9;
        int s   = packed & 511;
        uint32_t base = ((uint32_t)pos) << 9;
        uint32_t m2s[N_STEPS] = { ma.x, ma.y, ma.z, ma.w, mb };

        #pragma unroll
        for (int t = 0; t < N_STEPS; t++) {
            if (m2s[t] < g_pubm[s])          // exact reject bound (warp-uniform)
                s = do_step(s, base, m2s[t], K.k1a[t], K.k1b[t], lane);
        }

        if (lane == 0) outf[pos] = (float)s;
    }
}

// ===================== launch =====================
extern "C" void kernel_launch(void* const* d_in, const int* in_sizes, int n_in,
                              void* d_out, int out_size) {
    (void)out_size;
    // -------- dual-convention size mapping (elements OR bytes) --------
    bool has_e_w1=false, has_e_b1=false, has_e_w2=false, has_e_b2=false;
    bool has_b_w1=false, has_b_b1=false, has_b_w2=false, has_b_b2=false;
    for (int i = 0; i < n_in; i++) {
        int sz = in_sizes[i];
        if (sz == 16384)  has_e_w1 = true;
        if (sz == 64)     has_e_b1 = true;
        if (sz == 32768)  has_e_w2 = true;
        if (sz == 512)    has_e_b2 = true;
        if (sz == 65536)  has_b_w1 = true;
        if (sz == 256)    has_b_b1 = true;
        if (sz == 131072) has_b_w2 = true;
        if (sz == 2048)   has_b_b2 = true;
    }
    bool elems_mode = has_e_w1 && has_e_b1 && has_e_w2 && has_e_b2;
    bool bytes_mode = !elems_mode && has_b_w1 && has_b_b1 && has_b_w2 && has_b_b2;

    const float *W1 = nullptr, *b1 = nullptr, *W2 = nullptr, *b2 = nullptr;
    const void  *cand[2] = { nullptr, nullptr };
    int ncand = 0;

    int s_w1 = elems_mode ? 16384  : 65536;
    int s_b1 = elems_mode ? 64     : 256;
    int s_w2 = elems_mode ? 32768  : 131072;
    int s_b2 = elems_mode ? 512    : 2048;
    int s_xe = elems_mode ? 131072 : 524288;

    if (elems_mode || bytes_mode) {
        for (int i = 0; i < n_in; i++) {
            int sz = in_sizes[i];
            if      (sz == s_w1) W1 = (const float*)d_in[i];
            else if (sz == s_b1) b1 = (const float*)d_in[i];
            else if (sz == s_w2) W2 = (const float*)d_in[i];
            else if (sz == s_b2) b2 = (const float*)d_in[i];
            else if (sz == s_xe) { if (ncand < 2) cand[ncand++] = d_in[i]; }
        }
    }

    bool ok = (elems_mode || bytes_mode) && W1 && b1 && W2 && b2 && ncand == 2;
    if (!ok) {
        k_fallback<<<(N_POS + 255) / 256, 256>>>((float*)d_out);
        return;
    }
    const uint32_t *bufA = (const uint32_t*)cand[0];
    const uint32_t *bufB = (const uint32_t*)cand[1];
    float* outf = (float*)d_out;

    // -------- per-step keys (jax.random.key(42), partitionable fold-like) -----
    KeysT K;
    for (int i = 0; i < N_STEPS; i++) {
        uint32_t sk0, sk1;
        h_tf2x32(0u, 42u, 0u, (uint32_t)i, sk0, sk1);
        h_tf2x32(sk0, sk1, 0u, 0u, K.k1a[i], K.k1b[i]);
        h_tf2x32(sk0, sk1, 0u, 1u, K.k2a[i], K.k2b[i]);
    }

    k_table_fused<<<VOCAB, 256>>>(bufA, bufB, W1, b1, W2, b2);
    k_scan<<<N_POS / 256, 256>>>(bufA, bufB, outf, K);
    k_work<<<4096, 128>>>(outf, K);
}

// round 17
// speedup vs baseline: 1.3233x; 1.3233x over previous
#include <cuda_runtime.h>
#include <cstdint>
#include <math.h>

// Problem constants (fixed by setup_inputs)
#define VOCAB   512
#define EMB     256
#define HID     64
#define N_POS   (32 * 4096)   // B * L = 131072
#define N_STEPS 5
#define DT_F32  0.01f         // float32(T_HORIZON / steps)
#define TINY_F  1.17549435082228750797e-38f  // finfo(float32).tiny
#define EPS2    1e-3f         // fast/exact margin; fast abs err <= ~1e-6 always
#define NEG_INF __int_as_float(0xff800000)
#define INV2P23 1.1920928955078125e-7f  // 2^-23 (exact)

struct KeysT { unsigned int k1a[5], k1b[5], k2a[5], k2b[5]; };

// -------- scratch: __device__ globals only --------
__device__ float    g_T[VOCAB * VOCAB];   // intensity table
__device__ uint32_t g_pubm[VOCAB];        // bits-space reject bound per state
__device__ int      g_qpk[N_POS];         // queue: packed (pos<<9)|s0
__device__ uint4    g_qm2a[N_POS];        // queue: m2[0..3]
__device__ uint32_t g_qm2b[N_POS];        // queue: m2[4]
__device__ int      g_qcnt;               // flagged count (zeroed by table kernel)

// ===================== threefry-2x32 (exact JAX schedule) =====================
__device__ __forceinline__ void tf_round(uint32_t& x0, uint32_t& x1, int r) {
    x0 += x1;
    x1 = __funnelshift_l(x1, x1, r);
    x1 ^= x0;
}

__device__ __forceinline__ uint2 tf2x32(uint32_t k0, uint32_t k1,
                                        uint32_t x0, uint32_t x1) {
    uint32_t ks2 = k0 ^ k1 ^ 0x1BD11BDAu;
    x0 += k0; x1 += k1;
    tf_round(x0,x1,13); tf_round(x0,x1,15); tf_round(x0,x1,26); tf_round(x0,x1, 6);
    x0 += k1;  x1 += ks2 + 1u;
    tf_round(x0,x1,17); tf_round(x0,x1,29); tf_round(x0,x1,16); tf_round(x0,x1,24);
    x0 += ks2; x1 += k0 + 2u;
    tf_round(x0,x1,13); tf_round(x0,x1,15); tf_round(x0,x1,26); tf_round(x0,x1, 6);
    x0 += k0;  x1 += k1 + 3u;
    tf_round(x0,x1,17); tf_round(x0,x1,29); tf_round(x0,x1,16); tf_round(x0,x1,24);
    x0 += k1;  x1 += ks2 + 4u;
    tf_round(x0,x1,13); tf_round(x0,x1,15); tf_round(x0,x1,26); tf_round(x0,x1, 6);
    x0 += ks2; x1 += k0 + 5u;
    return make_uint2(x0, x1);
}

static inline uint32_t h_rotl(uint32_t x, int r) { return (x << r) | (x >> (32 - r)); }
static void h_tf2x32(uint32_t k0, uint32_t k1, uint32_t x0, uint32_t x1,
                     uint32_t& o0, uint32_t& o1) {
    uint32_t ks2 = k0 ^ k1 ^ 0x1BD11BDAu;
    static const int R[20] = {13,15,26,6, 17,29,16,24, 13,15,26,6, 17,29,16,24, 13,15,26,6};
    x0 += k0; x1 += k1;
    const uint32_t ks[3] = {k0, k1, ks2};
    for (int g = 0; g < 5; g++) {
        for (int j = 0; j < 4; j++) {
            int r = R[g * 4 + j];
            x0 += x1; x1 = h_rotl(x1, r); x1 ^= x0;
        }
        x0 += ks[(g + 1) % 3];
        x1 += ks[(g + 2) % 3] + (uint32_t)(g + 1);
    }
    o0 = x0; o1 = x1;
}

// partitionable random_bits(32): counter (hi=0, lo=idx), out = o0 ^ o1
__device__ __forceinline__ uint32_t jax_bits32(uint32_t k0, uint32_t k1, uint32_t idx) {
    uint2 r = tf2x32(k0, k1, 0u, idx);
    return r.x ^ r.y;
}

__device__ __forceinline__ float bits_to_u01(uint32_t bits) {
    return __uint_as_float((bits >> 9) | 0x3f800000u) - 1.0f;
}

// bits-space accept threshold (monotone in T); 512 calls total (table kernel)
__device__ __noinline__ uint32_t thr_of(float T) {
    float p = T * DT_F32;
    float e = (float)exp(-(double)p);          // correctly-rounded f32 exp
    float a = 1.0f - e;                        // exact (Sterbenz, e in [0.9,1.1])
    double d = ceil((double)a * 8388608.0);
    d = fmin(fmax(d, 0.0), 8388608.0);
    return (uint32_t)d;
}

// exact accept decision, DP reference chain (rare fallback only)
__device__ __noinline__ bool dp_accept(float T, float u2f) {
    float p = T * DT_F32;
    float e = (float)exp(-(double)p);          // correctly-rounded f32 exp
    float a = 1.0f - e;                        // the reference accept prob
    return u2f < a;                            // u2f == reference u2 bit-exactly
}

// fast gumbel, abs err <= ~1e-6 for ALL u: series in exact d=1-u01 near u->1
__device__ __forceinline__ float gumbel_fast2(float u01, float u) {
    float x;
    if (u01 > 0.99f) {
        float d = 1.0f - u01;   // exact (Sterbenz)
        x = d * fmaf(d, fmaf(d, fmaf(d, 0.25f, 0.33333333f), 0.5f), 1.0f);
    } else {
        x = -__logf(u);
    }
    return -__logf(x);
}

// pass 2 (rare): CR-exact resolve among candidates within EPS2 of the fast max.
__device__ __noinline__ int resolve_exact(const float* __restrict__ row,
                                          uint32_t base, int s,
                                          uint32_t k1a, uint32_t k1b,
                                          float m1, int lane) {
    float e1 = NEG_INF;
    int   ei = VOCAB;
    for (int i = 0; i < 16; i++) {
        int v = (i << 5) + lane;
        if (v == s) continue;
        uint32_t bits = jax_bits32(k1a, k1b, base + (uint32_t)v);
        float u01 = bits_to_u01(bits);
        float u = fmaxf(TINY_F, u01 + TINY_F);
        float candf = row[v] + gumbel_fast2(u01, u);
        if (candf < m1 - EPS2) continue;           // provably not the max
        float r1 = (float)log((double)u);          // CR f32 log
        float r2 = (float)log((double)(-r1));      // CR f32 log
        float cand = row[v] - r2;                  // exact reference chain
        if (cand > e1) { e1 = cand; ei = v; }      // ascending v: first tie
    }
    #pragma unroll
    for (int off = 16; off; off >>= 1) {
        float ov = __shfl_xor_sync(0xffffffffu, e1, off);
        int   oi = __shfl_xor_sync(0xffffffffu, ei, off);
        if (ov > e1 || (ov == e1 && oi < ei)) { e1 = ov; ei = oi; }
    }
    return ei;
}

// one Gillespie step for one position (warp-collective, warp-uniform args).
// __noinline__: keeps the cold CR/DP paths from inflating the caller's regs.
__device__ __noinline__ int do_step(int s, uint32_t base, uint32_t m2,
                                    uint32_t k1a, uint32_t k1b, int lane) {
    const float* __restrict__ row = g_T + (s << 9);

    // ---- pass 1: pure-f32 fast gumbels, full ILP ----
    float m1 = NEG_INF, mm2 = NEG_INF;
    int   i1 = VOCAB;
    #pragma unroll
    for (int i = 0; i < 16; i++) {
        int v = (i << 5) + lane;
        uint32_t bits = jax_bits32(k1a, k1b, base + (uint32_t)v);
        float u01 = bits_to_u01(bits);
        float u = fmaxf(TINY_F, u01 + TINY_F);
        float g = gumbel_fast2(u01, u);
        float cand = (v == s) ? NEG_INF : (row[v] + g);
        if (cand > m1) { mm2 = m1; m1 = cand; i1 = v; }
        else if (cand > mm2) { mm2 = cand; }
    }
    #pragma unroll
    for (int off = 16; off; off >>= 1) {
        float o1 = __shfl_xor_sync(0xffffffffu, m1, off);
        int   oi = __shfl_xor_sync(0xffffffffu, i1, off);
        float o2 = __shfl_xor_sync(0xffffffffu, mm2, off);
        if (o1 > m1 || (o1 == m1 && oi < i1)) {
            mm2 = fmaxf(m1, o2); m1 = o1; i1 = oi;
        } else {
            mm2 = fmaxf(mm2, o1);
        }
    }
    int bidx = i1;

    // ---- pass 2 (rare, gap < EPS2): CR-exact resolve near the max ----
    if ((m1 - mm2) < EPS2)
        bidx = resolve_exact(row, base, s, k1a, k1b, m1, lane);

    // ---- accept: fast f32 compare, provable margin, rare DP fallback ----
    float T   = row[bidx];
    float u2f = (float)m2 * INV2P23;                 // exact == ref u2
    float af  = 1.0f - __expf(-(T * DT_F32));        // |af-a_ref| < ~5e-7
    bool acc;
    if (fabsf(u2f - af) > 1e-6f) acc = (u2f < af);   // certain
    else                         acc = dp_accept(T, u2f);
    return acc ? bidx : s;
}

// ===================== io kernels =====================
__global__ void k_fallback(float* __restrict__ out) {
    int i = blockIdx.x * blockDim.x + threadIdx.x;
    if (i < N_POS) out[i] = 1000.0f;
}

// warp-collective classification from a FIXED 32-word window (A[0..31], B[0..31]).
// All blocks read the same 128B -> one cold miss chip-wide, then L1/L2 hits.
// mode: 0 A=x(int), 1 A=x(f32), 2 B=x(int), 3 B=x(f32).
// Emb window passing a state-check: P ~ 0.16^32 ~ 3e-26. All-zero ambiguity
// decodes identically under both encodings.
__device__ __forceinline__ int warp_mode(const uint32_t* __restrict__ A,
                                         const uint32_t* __restrict__ B,
                                         int lane) {
    uint32_t wa = A[lane], wb = B[lane];
    int aInt = __all_sync(0xffffffffu, wa < 512u);
    int aF32 = __all_sync(0xffffffffu, wa == 0u ||
                          (wa >= 0x3f800000u && wa <= 0x43ff8000u));
    int bInt = __all_sync(0xffffffffu, wb < 512u);
    return aInt ? 0 : (aF32 ? 1 : (bInt ? 2 : 3));
}

// ===================== fused table kernel (one block per state) ===============
__global__ void __launch_bounds__(256)
k_table_fused(const uint32_t* __restrict__ A, const uint32_t* __restrict__ B,
              const float* __restrict__ W1, const float* __restrict__ b1,
              const float* __restrict__ W2, const float* __restrict__ b2) {
    __shared__ float sE[EMB];
    __shared__ float sH[HID];
    __shared__ float sMax[8];
    __shared__ int   sMode;
    int s = blockIdx.x;
    int tid = threadIdx.x;
    if (s == 0 && tid == 0) g_qcnt = 0;   // zero queue counter (runs before scan)

    if (tid < 32) {
        int mode = warp_mode(A, B, tid);
        if (tid == 0) sMode = mode;
    }
    __syncthreads();
    const float* emb = (const float*)((sMode < 2) ? B : A);   // the non-x buffer

    if (tid < EMB / 4)
        ((float4*)sE)[tid] = ((const float4*)(emb + s * EMB))[tid];
    __syncthreads();

    if (tid < HID) {
        float acc = 0.0f;
        #pragma unroll 16
        for (int k = 0; k < EMB; k++)
            acc = fmaf(sE[k], W1[k * HID + tid], acc);
        sH[tid] = fmaxf(acc + b1[tid], 0.0f);
    }
    __syncthreads();

    float tmax = NEG_INF;
    #pragma unroll
    for (int r = 0; r < 2; r++) {
        int v = tid + r * 256;
        float acc = 0.0f;
        #pragma unroll
        for (int j = 0; j < HID; j++)
            acc = fmaf(sH[j], W2[j * VOCAB + v], acc);
        float T = acc + b2[v];
        g_T[s * VOCAB + v] = T;
        if (v != s) tmax = fmaxf(tmax, T);
    }
    #pragma unroll
    for (int off = 16; off; off >>= 1)
        tmax = fmaxf(tmax, __shfl_xor_sync(0xffffffffu, tmax, off));
    if ((tid & 31) == 0) sMax[tid >> 5] = tmax;
    __syncthreads();
    if (tid == 0) {
        float m = NEG_INF;
        #pragma unroll
        for (int w = 0; w < 8; w++) m = fmaxf(m, sMax[w]);
        g_pubm[s] = thr_of(m);    // thr monotone in T -> exact row bound
    }
}

// ===================== scan: flag + store m2 payload =========================
// Exact: the FIRST accept must occur from s0, requiring m2_t < pubm[s0].
// Reads ONLY the x buffer (mode from the shared fixed window).
__global__ void __launch_bounds__(256)
k_scan(const uint32_t* __restrict__ A, const uint32_t* __restrict__ B,
       float* __restrict__ outf, KeysT K) {
    int lane = threadIdx.x & 31;
    int mode = warp_mode(A, B, lane);      // L1-hot after first warp
    const uint32_t* xp = (mode < 2) ? A : B;

    int i = blockIdx.x * 256 + threadIdx.x;
    uint32_t w = xp[i];
    int s0 = (mode & 1) ? (int)__uint_as_float(w) : (int)w;
    s0 = min(max(s0, 0), VOCAB - 1);
    outf[i] = (float)s0;

    uint32_t pb = g_pubm[s0];
    uint32_t m2[N_STEPS];
    bool flag = false;
    #pragma unroll
    for (int t = 0; t < N_STEPS; t++) {
        m2[t] = jax_bits32(K.k2a[t], K.k2b[t], (uint32_t)i) >> 9;
        flag |= (m2[t] < pb);
    }
    unsigned mask = __ballot_sync(0xffffffffu, flag);
    if (mask) {
        int leader = __ffs(mask) - 1;
        int baseIdx = 0;
        if (lane == leader) baseIdx = atomicAdd(&g_qcnt, __popc(mask));
        baseIdx = __shfl_sync(0xffffffffu, baseIdx, leader);
        if (flag) {
            int idx = baseIdx + __popc(mask & ((1u << lane) - 1));
            g_qpk[idx]  = (i << 9) | s0;
            g_qm2a[idx] = make_uint4(m2[0], m2[1], m2[2], m2[3]);
            g_qm2b[idx] = m2[4];
        }
    }
}

// ===================== worker: full 5-step trajectory per flagged position ====
__global__ void __launch_bounds__(128)
k_work(float* __restrict__ outf, KeysT K) {
    int gw    = blockIdx.x * 4 + (threadIdx.x >> 5);
    int lane  = threadIdx.x & 31;
    int nwarp = gridDim.x * 4;
    int qn    = min(g_qcnt, N_POS);

    for (int qi = gw; qi < qn; qi += nwarp) {
        int packed   = g_qpk[qi];
        uint4 ma     = g_qm2a[qi];
        uint32_t mb  = g_qm2b[qi];
        int pos = packed >> 9;
        int s   = packed & 511;
        uint32_t base = ((uint32_t)pos) << 9;
        uint32_t m2s[N_STEPS] = { ma.x, ma.y, ma.z, ma.w, mb };

        #pragma unroll
        for (int t = 0; t < N_STEPS; t++) {
            if (m2s[t] < g_pubm[s])          // exact reject bound (warp-uniform)
                s = do_step(s, base, m2s[t], K.k1a[t], K.k1b[t], lane);
        }

        if (lane == 0) outf[pos] = (float)s;
    }
}

// ===================== launch =====================
extern "C" void kernel_launch(void* const* d_in, const int* in_sizes, int n_in,
                              void* d_out, int out_size) {
    (void)out_size;
    // -------- dual-convention size mapping (elements OR bytes) --------
    bool has_e_w1=false, has_e_b1=false, has_e_w2=false, has_e_b2=false;
    bool has_b_w1=false, has_b_b1=false, has_b_w2=false, has_b_b2=false;
    for (int i = 0; i < n_in; i++) {
        int sz = in_sizes[i];
        if (sz == 16384)  has_e_w1 = true;
        if (sz == 64)     has_e_b1 = true;
        if (sz == 32768)  has_e_w2 = true;
        if (sz == 512)    has_e_b2 = true;
        if (sz == 65536)  has_b_w1 = true;
        if (sz == 256)    has_b_b1 = true;
        if (sz == 131072) has_b_w2 = true;
        if (sz == 2048)   has_b_b2 = true;
    }
    bool elems_mode = has_e_w1 && has_e_b1 && has_e_w2 && has_e_b2;
    bool bytes_mode = !elems_mode && has_b_w1 && has_b_b1 && has_b_w2 && has_b_b2;

    const float *W1 = nullptr, *b1 = nullptr, *W2 = nullptr, *b2 = nullptr;
    const void  *cand[2] = { nullptr, nullptr };
    int ncand = 0;

    int s_w1 = elems_mode ? 16384  : 65536;
    int s_b1 = elems_mode ? 64     : 256;
    int s_w2 = elems_mode ? 32768  : 131072;
    int s_b2 = elems_mode ? 512    : 2048;
    int s_xe = elems_mode ? 131072 : 524288;

    if (elems_mode || bytes_mode) {
        for (int i = 0; i < n_in; i++) {
            int sz = in_sizes[i];
            if      (sz == s_w1) W1 = (const float*)d_in[i];
            else if (sz == s_b1) b1 = (const float*)d_in[i];
            else if (sz == s_w2) W2 = (const float*)d_in[i];
            else if (sz == s_b2) b2 = (const float*)d_in[i];
            else if (sz == s_xe) { if (ncand < 2) cand[ncand++] = d_in[i]; }
        }
    }

    bool ok = (elems_mode || bytes_mode) && W1 && b1 && W2 && b2 && ncand == 2;
    if (!ok) {
        k_fallback<<<(N_POS + 255) / 256, 256>>>((float*)d_out);
        return;
    }
    const uint32_t *bufA = (const uint32_t*)cand[0];
    const uint32_t *bufB = (const uint32_t*)cand[1];
    float* outf = (float*)d_out;

    // -------- per-step keys (jax.random.key(42), partitionable fold-like) -----
    KeysT K;
    for (int i = 0; i < N_STEPS; i++) {
        uint32_t sk0, sk1;
        h_tf2x32(0u, 42u, 0u, (uint32_t)i, sk0, sk1);
        h_tf2x32(sk0, sk1, 0u, 0u, K.k1a[i], K.k1b[i]);
        h_tf2x32(sk0, sk1, 0u, 1u, K.k2a[i], K.k2b[i]);
    }

    k_table_fused<<<VOCAB, 256>>>(bufA, bufB, W1, b1, W2, b2);
    k_scan<<<N_POS / 256, 256>>>(bufA, bufB, outf, K);
    k_work<<<4096, 128>>>(outf, K);
}